// round 10
// baseline (speedup 1.0000x reference)
#include <cuda_runtime.h>
#include <cuda_bf16.h>
#include <mma.h>
#include <math.h>
#include <stdint.h>

using namespace nvcuda;

#define NP     1024
#define EMBD   64
#define HID    128
#define NCELL  64
#define PN     4096     // NCELL * EMBD
#define KX     256      // [emb(64) | pool(64) | h0(128)]
#define MIX    20
#define NOUT   120

// ---------------- device scratch (static, no allocations) ----------------
__device__ float g_P[NP * PN];        // 16 MB
__device__ float g_X[NP * KX];        // 1 MB
__device__ float g_h[NP * HID];       // 0.5 MB

__device__ __forceinline__ float sigm(float x) { return 1.0f / (1.0f + expf(-x)); }

// split one float4 into hi/lo bf16x2 pairs and store to smem
__device__ __forceinline__ void split_store(__nv_bfloat16* d1, __nv_bfloat16* d2, float4 v) {
    __nv_bfloat162 h1a, h1b, h2a, h2b;
    h1a.x = __float2bfloat16(v.x); h2a.x = __float2bfloat16(v.x - __bfloat162float(h1a.x));
    h1a.y = __float2bfloat16(v.y); h2a.y = __float2bfloat16(v.y - __bfloat162float(h1a.y));
    h1b.x = __float2bfloat16(v.z); h2b.x = __float2bfloat16(v.z - __bfloat162float(h1b.x));
    h1b.y = __float2bfloat16(v.w); h2b.y = __float2bfloat16(v.w - __bfloat162float(h1b.y));
    *(__nv_bfloat162*)(d1)     = h1a;
    *(__nv_bfloat162*)(d1 + 2) = h1b;
    *(__nv_bfloat162*)(d2)     = h2a;
    *(__nv_bfloat162*)(d2 + 2) = h2b;
}

// ============ K1: WMMA bf16 P-GEMM, 3-buffer smem (2 CTAs/SM) ============
// P = A1@B1^T + A2@B1^T + A1@B2^T, fp32 acc. CTA tile 128x128, K=128 resident.
#define LDP 136
#define TILEP (128 * LDP)
#define SMEM_P_BYTES (3 * TILEP * 2)   // 104448 B

__global__ __launch_bounds__(256, 2) void mma_P_kernel(const float* __restrict__ h0,
                                                       const float* __restrict__ Wsoc) {
    extern __shared__ __align__(16) __nv_bfloat16 smemP[];
    __nv_bfloat16* sA1 = smemP;
    __nv_bfloat16* sA2 = smemP + TILEP;
    __nv_bfloat16* sB  = smemP + 2 * TILEP;   // holds B1, then B2

    const int t   = threadIdx.x;
    const int wid = t >> 5;
    const int warp_m = wid & 1;
    const int warp_n = wid >> 1;
    const int row0 = blockIdx.x * 128;
    const int col0 = blockIdx.y * 128;

    // A tiles (hi + residual)
    #pragma unroll
    for (int i = t; i < 4096; i += 256) {
        const int row = i >> 5, k4 = i & 31;
        const float4 v = *(const float4*)&h0[(row0 + row) * HID + k4 * 4];
        split_store(sA1 + row * LDP + k4 * 4, sA2 + row * LDP + k4 * 4, v);
    }
    // B1 tile (hi); keep residual in registers? No — recompute on 2nd pass.
    #pragma unroll
    for (int i = t; i < 4096; i += 256) {
        const int row = i >> 5, k4 = i & 31;
        const int ce = col0 + row;
        const int e = ce & 63, c = ce >> 6;
        const float4 v = *(const float4*)&Wsoc[e * (NCELL * HID) + c * HID + k4 * 4];
        __nv_bfloat162 h1a, h1b;
        h1a.x = __float2bfloat16(v.x); h1a.y = __float2bfloat16(v.y);
        h1b.x = __float2bfloat16(v.z); h1b.y = __float2bfloat16(v.w);
        *(__nv_bfloat162*)(sB + row * LDP + k4 * 4)     = h1a;
        *(__nv_bfloat162*)(sB + row * LDP + k4 * 4 + 2) = h1b;
    }
    __syncthreads();

    wmma::fragment<wmma::accumulator, 16, 16, 16, float> acc[4][2];
    #pragma unroll
    for (int i = 0; i < 4; i++)
        #pragma unroll
        for (int j = 0; j < 2; j++)
            wmma::fill_fragment(acc[i][j], 0.0f);

    wmma::fragment<wmma::matrix_a, 16, 16, 16, __nv_bfloat16, wmma::row_major> af;
    wmma::fragment<wmma::matrix_b, 16, 16, 16, __nv_bfloat16, wmma::col_major> bf[2];

    // terms A1@B1 and A2@B1
    #pragma unroll
    for (int term = 0; term < 2; term++) {
        const __nv_bfloat16* sA = (term == 0) ? sA1 : sA2;
        #pragma unroll
        for (int k0 = 0; k0 < 8; k0++) {
            #pragma unroll
            for (int j = 0; j < 2; j++)
                wmma::load_matrix_sync(bf[j], sB + (warp_n * 32 + j * 16) * LDP + k0 * 16, LDP);
            #pragma unroll
            for (int i = 0; i < 4; i++) {
                wmma::load_matrix_sync(af, sA + (warp_m * 64 + i * 16) * LDP + k0 * 16, LDP);
                wmma::mma_sync(acc[i][0], af, bf[0], acc[i][0]);
                wmma::mma_sync(acc[i][1], af, bf[1], acc[i][1]);
            }
        }
    }
    __syncthreads();
    // overwrite sB with B2 (residual)
    #pragma unroll
    for (int i = t; i < 4096; i += 256) {
        const int row = i >> 5, k4 = i & 31;
        const int ce = col0 + row;
        const int e = ce & 63, c = ce >> 6;
        const float4 v = *(const float4*)&Wsoc[e * (NCELL * HID) + c * HID + k4 * 4];
        __nv_bfloat162 h2a, h2b;
        h2a.x = __float2bfloat16(v.x - __bfloat162float(__float2bfloat16(v.x)));
        h2a.y = __float2bfloat16(v.y - __bfloat162float(__float2bfloat16(v.y)));
        h2b.x = __float2bfloat16(v.z - __bfloat162float(__float2bfloat16(v.z)));
        h2b.y = __float2bfloat16(v.w - __bfloat162float(__float2bfloat16(v.w)));
        *(__nv_bfloat162*)(sB + row * LDP + k4 * 4)     = h2a;
        *(__nv_bfloat162*)(sB + row * LDP + k4 * 4 + 2) = h2b;
    }
    __syncthreads();

    // term A1@B2
    #pragma unroll
    for (int k0 = 0; k0 < 8; k0++) {
        #pragma unroll
        for (int j = 0; j < 2; j++)
            wmma::load_matrix_sync(bf[j], sB + (warp_n * 32 + j * 16) * LDP + k0 * 16, LDP);
        #pragma unroll
        for (int i = 0; i < 4; i++) {
            wmma::load_matrix_sync(af, sA1 + (warp_m * 64 + i * 16) * LDP + k0 * 16, LDP);
            wmma::mma_sync(acc[i][0], af, bf[0], acc[i][0]);
            wmma::mma_sync(acc[i][1], af, bf[1], acc[i][1]);
        }
    }

    #pragma unroll
    for (int i = 0; i < 4; i++)
        #pragma unroll
        for (int j = 0; j < 2; j++) {
            float* dst = g_P + (size_t)(row0 + warp_m * 64 + i * 16) * PN
                             + col0 + warp_n * 32 + j * 16;
            wmma::store_matrix_sync(dst, acc[i][j], PN, wmma::mem_row_major);
        }
}

// ============ K2: pair gather + X assembly (512 threads per pedestrian n) ============
__global__ __launch_bounds__(512) void scatter_kernel(const float* __restrict__ xabs,
                                                      const float* __restrict__ h0,
                                                      const float* __restrict__ W_emb,
                                                      const float* __restrict__ b_emb,
                                                      const float* __restrict__ b_soc) {
    __shared__ float sx[NP];
    __shared__ float sy[NP];
    __shared__ int   slist[NP];
    __shared__ int   wcnt[16];
    __shared__ float sred[8][64];

    const int n = blockIdx.x;
    const int t = threadIdx.x;
    const int w = t >> 5;
    const int lane = t & 31;

    for (int i = t; i < NP; i += 512) {
        const float2 v = ((const float2*)xabs)[i];
        sx[i] = v.x;
        sy[i] = v.y;
    }
    __syncthreads();

    const float wl = sx[n] - 0.2f;
    const float bl = sy[n] - 0.2f;

    int cells[2];
    unsigned masks[2];
    int cnt = 0;
    #pragma unroll
    for (int j = 0; j < 2; j++) {
        const int m = w * 64 + j * 32 + lane;
        const float dx = sx[m] - wl;
        const float dy = sy[m] - bl;
        int cell = -1;
        if (dx >= 0.0f && dx < 0.4f && dy >= 0.0f && dy < 0.4f && m != n) {
            const int cx = (int)floorf(__fmul_rn(__fdiv_rn(dx, 0.4f), 8.0f));
            const int cy = (int)floorf(__fmul_rn(__fdiv_rn(dy, 0.4f), 8.0f));
            if (cx >= 0 && cx < 8 && cy >= 0 && cy < 8) cell = cx + cy * 8;
        }
        cells[j] = (cell >= 0) ? (m * PN + cell * EMBD) : -1;
        masks[j] = __ballot_sync(0xFFFFFFFFu, cell >= 0);
        cnt += __popc(masks[j]);
    }
    if (lane == 0) wcnt[w] = cnt;

    if (t < 128) {
        g_X[n * KX + 128 + t] = h0[n * HID + t];
    } else if (t < 192) {
        const int e2 = t - 128;
        const float e = sx[n] * W_emb[2 * e2] + sy[n] * W_emb[2 * e2 + 1] + b_emb[e2];
        g_X[n * KX + e2] = fmaxf(e, 0.0f);
    }
    __syncthreads();

    int base = 0, tot = 0;
    #pragma unroll
    for (int ww = 0; ww < 16; ww++) {
        if (ww < w) base += wcnt[ww];
        tot += wcnt[ww];
    }
    #pragma unroll
    for (int j = 0; j < 2; j++) {
        if (cells[j] >= 0) {
            slist[base + __popc(masks[j] & ((1u << lane) - 1u))] = cells[j];
        }
        base += __popc(masks[j]);
    }
    __syncthreads();

    // gather: 8 slots x 64 e, unroll 4 (independent L2 chains)
    const int slot = t >> 6;
    const int e    = t & 63;
    float a0 = 0.0f, a1 = 0.0f, a2 = 0.0f, a3 = 0.0f;
    int i = slot;
    for (; i + 32 <= tot; i += 32) {
        a0 += g_P[(size_t)slist[i]      + e];
        a1 += g_P[(size_t)slist[i + 8]  + e];
        a2 += g_P[(size_t)slist[i + 16] + e];
        a3 += g_P[(size_t)slist[i + 24] + e];
    }
    for (; i < tot; i += 8) a0 += g_P[(size_t)slist[i] + e];
    sred[slot][e] = (a0 + a1) + (a2 + a3);
    __syncthreads();

    if (t < 64) {
        float s = b_soc[e];
        #pragma unroll
        for (int sl = 0; sl < 8; sl++) s += sred[sl][e];
        g_X[n * KX + 64 + e] = fmaxf(s, 0.0f);
    }
}

// ============ K3: WMMA gates GEMM fused with LSTM cell ============
#define LDG2  264
#define TILEG (64 * LDG2)
#define SMEM_G_BYTES (4 * TILEG * 2 + 64 * 68 * 4)

__global__ __launch_bounds__(256, 1) void gates_lstm_kernel(const float* __restrict__ W_ih,
                                                            const float* __restrict__ W_hh,
                                                            const float* __restrict__ b_ih,
                                                            const float* __restrict__ b_hh,
                                                            const float* __restrict__ c0) {
    extern __shared__ __align__(16) __nv_bfloat16 smemG[];
    __nv_bfloat16* sA1 = smemG;
    __nv_bfloat16* sA2 = smemG + TILEG;
    __nv_bfloat16* sB1 = smemG + 2 * TILEG;
    __nv_bfloat16* sB2 = smemG + 3 * TILEG;
    float* sg = (float*)(smemG + 4 * TILEG);

    const int row0 = blockIdx.x * 64;
    const int d0   = blockIdx.y * 16;
    const int t   = threadIdx.x;
    const int wid = t >> 5;
    const int warp_m = wid & 3;
    const int warp_n = wid >> 2;

    #pragma unroll
    for (int i = t; i < 4096; i += 256) {
        const int row = i >> 6, k4 = i & 63;
        const float4 v = *(const float4*)&g_X[(row0 + row) * KX + k4 * 4];
        split_store(sA1 + row * LDG2 + k4 * 4, sA2 + row * LDG2 + k4 * 4, v);
    }
    #pragma unroll
    for (int i = t; i < 4096; i += 256) {
        const int cc = i >> 6, k4 = i & 63;
        const int wrow = (cc >> 4) * 128 + d0 + (cc & 15);
        const float4 v = (k4 < 32) ? *(const float4*)&W_ih[wrow * 128 + k4 * 4]
                                   : *(const float4*)&W_hh[wrow * 128 + (k4 - 32) * 4];
        split_store(sB1 + cc * LDG2 + k4 * 4, sB2 + cc * LDG2 + k4 * 4, v);
    }
    __syncthreads();

    wmma::fragment<wmma::accumulator, 16, 16, 16, float> acc[2];
    wmma::fill_fragment(acc[0], 0.0f);
    wmma::fill_fragment(acc[1], 0.0f);
    wmma::fragment<wmma::matrix_a, 16, 16, 16, __nv_bfloat16, wmma::row_major> af;
    wmma::fragment<wmma::matrix_b, 16, 16, 16, __nv_bfloat16, wmma::col_major> bf[2];

    #pragma unroll
    for (int term = 0; term < 3; term++) {
        const __nv_bfloat16* sA = (term == 1) ? sA2 : sA1;
        const __nv_bfloat16* sB = (term == 2) ? sB2 : sB1;
        #pragma unroll
        for (int k0 = 0; k0 < 16; k0++) {
            wmma::load_matrix_sync(af, sA + (warp_m * 16) * LDG2 + k0 * 16, LDG2);
            #pragma unroll
            for (int j = 0; j < 2; j++) {
                wmma::load_matrix_sync(bf[j], sB + (warp_n * 32 + j * 16) * LDG2 + k0 * 16, LDG2);
                wmma::mma_sync(acc[j], af, bf[j], acc[j]);
            }
        }
    }

    #pragma unroll
    for (int j = 0; j < 2; j++)
        wmma::store_matrix_sync(sg + (warp_m * 16) * 68 + warp_n * 32 + j * 16,
                                acc[j], 68, wmma::mem_row_major);
    __syncthreads();

    #pragma unroll
    for (int idx = t; idx < 1024; idx += 256) {
        const int rl = idx >> 4;
        const int dd = idx & 15;
        const int d = d0 + dd;
        const float ig = sg[rl * 68 + dd]      + b_ih[d]       + b_hh[d];
        const float fg = sg[rl * 68 + 16 + dd] + b_ih[128 + d] + b_hh[128 + d];
        const float gg = sg[rl * 68 + 32 + dd] + b_ih[256 + d] + b_hh[256 + d];
        const float og = sg[rl * 68 + 48 + dd] + b_ih[384 + d] + b_hh[384 + d];
        const int n = row0 + rl;
        const float c = sigm(fg) * c0[n * HID + d] + sigm(ig) * tanhf(gg);
        g_h[n * HID + d] = sigm(og) * tanhf(c);
    }
}

// ============ K4: WMMA output projection (16 rows x 64 cols, 256 threads) ============
#define LDO 136

__global__ __launch_bounds__(256) void out_kernel(const float* __restrict__ W_out,
                                                  const float* __restrict__ b_out,
                                                  float* __restrict__ out) {
    __shared__ __align__(16) __nv_bfloat16 sA1[16 * LDO];
    __shared__ __align__(16) __nv_bfloat16 sA2[16 * LDO];
    __shared__ __align__(16) __nv_bfloat16 sB1[64 * LDO];
    __shared__ __align__(16) __nv_bfloat16 sB2[64 * LDO];
    __shared__ float so[16 * 68];

    const int row0 = blockIdx.x * 16;
    const int col0 = blockIdx.y * 64;
    const int t   = threadIdx.x;
    const int wid = t >> 5;

    #pragma unroll
    for (int i = t; i < 512; i += 256) {
        const int row = i >> 5, k4 = i & 31;
        const float4 v = *(const float4*)&g_h[(row0 + row) * HID + k4 * 4];
        split_store(sA1 + row * LDO + k4 * 4, sA2 + row * LDO + k4 * 4, v);
    }
    #pragma unroll
    for (int i = t; i < 2048; i += 256) {
        const int ee = i >> 5, k4 = i & 31;
        const int eg = col0 + ee;
        const float4 v = (eg < NOUT) ? *(const float4*)&W_out[eg * HID + k4 * 4]
                                     : make_float4(0.f, 0.f, 0.f, 0.f);
        split_store(sB1 + ee * LDO + k4 * 4, sB2 + ee * LDO + k4 * 4, v);
    }
    __syncthreads();

    if (wid < 4) {
        wmma::fragment<wmma::accumulator, 16, 16, 16, float> acc;
        wmma::fill_fragment(acc, 0.0f);
        wmma::fragment<wmma::matrix_a, 16, 16, 16, __nv_bfloat16, wmma::row_major> af;
        wmma::fragment<wmma::matrix_b, 16, 16, 16, __nv_bfloat16, wmma::col_major> bf;
        #pragma unroll
        for (int term = 0; term < 3; term++) {
            const __nv_bfloat16* sA = (term == 1) ? sA2 : sA1;
            const __nv_bfloat16* sB = (term == 2) ? sB2 : sB1;
            #pragma unroll
            for (int k0 = 0; k0 < 8; k0++) {
                wmma::load_matrix_sync(af, sA + k0 * 16, LDO);
                wmma::load_matrix_sync(bf, sB + (wid * 16) * LDO + k0 * 16, LDO);
                wmma::mma_sync(acc, af, bf, acc);
            }
        }
        wmma::store_matrix_sync(so + wid * 16, acc, 68, wmma::mem_row_major);
    }
    __syncthreads();

    #pragma unroll
    for (int idx = t; idx < 16 * 64; idx += 256) {
        const int r  = idx >> 6;
        const int cc = idx & 63;
        const int e  = col0 + cc;
        if (e < NOUT) {
            const float v = so[r * 68 + cc] + b_out[e];
            out[(e / MIX) * (NP * MIX) + (row0 + r) * MIX + (e % MIX)] = v;
        }
    }
}

// ---------------- launch ----------------
extern "C" void kernel_launch(void* const* d_in, const int* in_sizes, int n_in,
                              void* d_out, int out_size) {
    const float* xabs  = (const float*)d_in[0];
    const float* h0    = (const float*)d_in[1];
    const float* c0    = (const float*)d_in[2];
    const float* W_emb = (const float*)d_in[3];
    const float* b_emb = (const float*)d_in[4];
    const float* W_soc = (const float*)d_in[5];
    const float* b_soc = (const float*)d_in[6];
    const float* W_ih  = (const float*)d_in[7];
    const float* W_hh  = (const float*)d_in[8];
    const float* b_ih  = (const float*)d_in[9];
    const float* b_hh  = (const float*)d_in[10];
    const float* W_out = (const float*)d_in[11];
    const float* b_out = (const float*)d_in[12];
    float* out = (float*)d_out;

    cudaFuncSetAttribute(mma_P_kernel, cudaFuncAttributeMaxDynamicSharedMemorySize, SMEM_P_BYTES);
    cudaFuncSetAttribute(gates_lstm_kernel, cudaFuncAttributeMaxDynamicSharedMemorySize, SMEM_G_BYTES);

    mma_P_kernel<<<dim3(8, 32), 256, SMEM_P_BYTES>>>(h0, W_soc);
    scatter_kernel<<<NP, 512>>>(xabs, h0, W_emb, b_emb, b_soc);
    gates_lstm_kernel<<<dim3(16, 8), 256, SMEM_G_BYTES>>>(W_ih, W_hh, b_ih, b_hh, c0);
    out_kernel<<<dim3(64, 2), 256>>>(W_out, b_out, out);
}

// round 11
// speedup vs baseline: 1.7159x; 1.7159x over previous
#include <cuda_runtime.h>
#include <cuda_bf16.h>
#include <mma.h>
#include <math.h>
#include <stdint.h>

using namespace nvcuda;

#define NP     1024
#define EMBD   64
#define HID    128
#define NCELL  64
#define PN     4096     // NCELL * EMBD
#define KX     256      // [emb(64) | pool(64) | h0(128)]
#define MIX    20
#define NOUT   120

// ---------------- device scratch (static, no allocations) ----------------
__device__ float g_P[NP * PN];        // 16 MB
__device__ float g_X[NP * KX];        // 1 MB
__device__ float g_h[NP * HID];       // 0.5 MB

__device__ __forceinline__ float sigm(float x) { return 1.0f / (1.0f + expf(-x)); }

// PDL: signal dependents may launch / wait for predecessor's memory visibility
#define PDL_TRIGGER() asm volatile("griddepcontrol.launch_dependents;" ::: "memory")
#define PDL_WAIT()    asm volatile("griddepcontrol.wait;" ::: "memory")

// split one float4 into hi/lo bf16x2 pairs and store to smem
__device__ __forceinline__ void split_store(__nv_bfloat16* d1, __nv_bfloat16* d2, float4 v) {
    __nv_bfloat162 h1a, h1b, h2a, h2b;
    h1a.x = __float2bfloat16(v.x); h2a.x = __float2bfloat16(v.x - __bfloat162float(h1a.x));
    h1a.y = __float2bfloat16(v.y); h2a.y = __float2bfloat16(v.y - __bfloat162float(h1a.y));
    h1b.x = __float2bfloat16(v.z); h2b.x = __float2bfloat16(v.z - __bfloat162float(h1b.x));
    h1b.y = __float2bfloat16(v.w); h2b.y = __float2bfloat16(v.w - __bfloat162float(h1b.y));
    *(__nv_bfloat162*)(d1)     = h1a;
    *(__nv_bfloat162*)(d1 + 2) = h1b;
    *(__nv_bfloat162*)(d2)     = h2a;
    *(__nv_bfloat162*)(d2 + 2) = h2b;
}

// ============ K1: WMMA bf16 P-GEMM (exact R7 version, 4 buffers, no reg cap) ============
#define LDP 136
#define TILEP (128 * LDP)
#define SMEM_P_BYTES (4 * TILEP * 2)

__global__ __launch_bounds__(256, 1) void mma_P_kernel(const float* __restrict__ h0,
                                                       const float* __restrict__ Wsoc) {
    extern __shared__ __align__(16) __nv_bfloat16 smemP[];
    __nv_bfloat16* sA1 = smemP;
    __nv_bfloat16* sA2 = smemP + TILEP;
    __nv_bfloat16* sB1 = smemP + 2 * TILEP;
    __nv_bfloat16* sB2 = smemP + 3 * TILEP;

    const int t   = threadIdx.x;
    const int wid = t >> 5;
    const int warp_m = wid & 1;
    const int warp_n = wid >> 1;
    const int row0 = blockIdx.x * 128;
    const int col0 = blockIdx.y * 128;

    if (t == 0) PDL_TRIGGER();

    #pragma unroll
    for (int i = t; i < 4096; i += 256) {
        const int row = i >> 5, k4 = i & 31;
        const float4 v = *(const float4*)&h0[(row0 + row) * HID + k4 * 4];
        split_store(sA1 + row * LDP + k4 * 4, sA2 + row * LDP + k4 * 4, v);
    }
    #pragma unroll
    for (int i = t; i < 4096; i += 256) {
        const int row = i >> 5, k4 = i & 31;
        const int ce = col0 + row;
        const int e = ce & 63, c = ce >> 6;
        const float4 v = *(const float4*)&Wsoc[e * (NCELL * HID) + c * HID + k4 * 4];
        split_store(sB1 + row * LDP + k4 * 4, sB2 + row * LDP + k4 * 4, v);
    }
    __syncthreads();

    wmma::fragment<wmma::accumulator, 16, 16, 16, float> acc[4][2];
    #pragma unroll
    for (int i = 0; i < 4; i++)
        #pragma unroll
        for (int j = 0; j < 2; j++)
            wmma::fill_fragment(acc[i][j], 0.0f);

    wmma::fragment<wmma::matrix_a, 16, 16, 16, __nv_bfloat16, wmma::row_major> af;
    wmma::fragment<wmma::matrix_b, 16, 16, 16, __nv_bfloat16, wmma::col_major> bf[2];

    #pragma unroll
    for (int term = 0; term < 3; term++) {
        const __nv_bfloat16* sA = (term == 1) ? sA2 : sA1;
        const __nv_bfloat16* sB = (term == 2) ? sB2 : sB1;
        #pragma unroll
        for (int k0 = 0; k0 < 8; k0++) {
            #pragma unroll
            for (int j = 0; j < 2; j++)
                wmma::load_matrix_sync(bf[j], sB + (warp_n * 32 + j * 16) * LDP + k0 * 16, LDP);
            #pragma unroll
            for (int i = 0; i < 4; i++) {
                wmma::load_matrix_sync(af, sA + (warp_m * 64 + i * 16) * LDP + k0 * 16, LDP);
                wmma::mma_sync(acc[i][0], af, bf[0], acc[i][0]);
                wmma::mma_sync(acc[i][1], af, bf[1], acc[i][1]);
            }
        }
    }

    #pragma unroll
    for (int i = 0; i < 4; i++)
        #pragma unroll
        for (int j = 0; j < 2; j++) {
            float* dst = g_P + (size_t)(row0 + warp_m * 64 + i * 16) * PN
                             + col0 + warp_n * 32 + j * 16;
            wmma::store_matrix_sync(dst, acc[i][j], PN, wmma::mem_row_major);
        }
}

// ============ K2: pair gather + X assembly (exact R7; PDL wait before P reads) ============
__global__ __launch_bounds__(512) void scatter_kernel(const float* __restrict__ xabs,
                                                      const float* __restrict__ h0,
                                                      const float* __restrict__ W_emb,
                                                      const float* __restrict__ b_emb,
                                                      const float* __restrict__ b_soc) {
    __shared__ float sx[NP];
    __shared__ float sy[NP];
    __shared__ int   slist[NP];
    __shared__ int   wcnt[16];
    __shared__ float sred[8][64];

    const int n = blockIdx.x;
    const int t = threadIdx.x;
    const int w = t >> 5;
    const int lane = t & 31;

    if (t == 0) PDL_TRIGGER();

    for (int i = t; i < NP; i += 512) {
        const float2 v = ((const float2*)xabs)[i];
        sx[i] = v.x;
        sy[i] = v.y;
    }
    __syncthreads();

    const float wl = sx[n] - 0.2f;
    const float bl = sy[n] - 0.2f;

    int cells[2];
    unsigned masks[2];
    int cnt = 0;
    #pragma unroll
    for (int j = 0; j < 2; j++) {
        const int m = w * 64 + j * 32 + lane;
        const float dx = sx[m] - wl;
        const float dy = sy[m] - bl;
        int cell = -1;
        if (dx >= 0.0f && dx < 0.4f && dy >= 0.0f && dy < 0.4f && m != n) {
            const int cx = (int)floorf(__fmul_rn(__fdiv_rn(dx, 0.4f), 8.0f));
            const int cy = (int)floorf(__fmul_rn(__fdiv_rn(dy, 0.4f), 8.0f));
            if (cx >= 0 && cx < 8 && cy >= 0 && cy < 8) cell = cx + cy * 8;
        }
        cells[j] = (cell >= 0) ? (m * PN + cell * EMBD) : -1;
        masks[j] = __ballot_sync(0xFFFFFFFFu, cell >= 0);
        cnt += __popc(masks[j]);
    }
    if (lane == 0) wcnt[w] = cnt;

    if (t < 128) {
        g_X[n * KX + 128 + t] = h0[n * HID + t];
    } else if (t < 192) {
        const int e2 = t - 128;
        const float e = sx[n] * W_emb[2 * e2] + sy[n] * W_emb[2 * e2 + 1] + b_emb[e2];
        g_X[n * KX + e2] = fmaxf(e, 0.0f);
    }
    __syncthreads();

    int base = 0, tot = 0;
    #pragma unroll
    for (int ww = 0; ww < 16; ww++) {
        if (ww < w) base += wcnt[ww];
        tot += wcnt[ww];
    }
    #pragma unroll
    for (int j = 0; j < 2; j++) {
        if (cells[j] >= 0) {
            slist[base + __popc(masks[j] & ((1u << lane) - 1u))] = cells[j];
        }
        base += __popc(masks[j]);
    }
    __syncthreads();

    PDL_WAIT();   // g_P must be complete before the gather

    const int slot = t >> 6;
    const int e    = t & 63;
    float acc = 0.0f;
    int i = slot;
    for (; i + 16 <= tot; i += 16) {
        acc += g_P[(size_t)slist[i] + e];
        acc += g_P[(size_t)slist[i + 8] + e];
    }
    for (; i < tot; i += 8) acc += g_P[(size_t)slist[i] + e];
    sred[slot][e] = acc;
    __syncthreads();

    if (t < 64) {
        float s = b_soc[e];
        #pragma unroll
        for (int sl = 0; sl < 8; sl++) s += sred[sl][e];
        g_X[n * KX + 64 + e] = fmaxf(s, 0.0f);
    }
}

// ============ K3: WMMA gates GEMM + LSTM (weights first, wait, then g_X) ============
#define LDG2  264
#define TILEG (64 * LDG2)
#define SMEM_G_BYTES (4 * TILEG * 2 + 64 * 68 * 4)

__global__ __launch_bounds__(256, 1) void gates_lstm_kernel(const float* __restrict__ W_ih,
                                                            const float* __restrict__ W_hh,
                                                            const float* __restrict__ b_ih,
                                                            const float* __restrict__ b_hh,
                                                            const float* __restrict__ c0) {
    extern __shared__ __align__(16) __nv_bfloat16 smemG[];
    __nv_bfloat16* sA1 = smemG;
    __nv_bfloat16* sA2 = smemG + TILEG;
    __nv_bfloat16* sB1 = smemG + 2 * TILEG;
    __nv_bfloat16* sB2 = smemG + 3 * TILEG;
    float* sg = (float*)(smemG + 4 * TILEG);

    const int row0 = blockIdx.x * 64;
    const int d0   = blockIdx.y * 16;
    const int t   = threadIdx.x;
    const int wid = t >> 5;
    const int warp_m = wid & 3;
    const int warp_n = wid >> 2;

    if (t == 0) PDL_TRIGGER();

    // independent prologue: weight tiles
    #pragma unroll
    for (int i = t; i < 4096; i += 256) {
        const int cc = i >> 6, k4 = i & 63;
        const int wrow = (cc >> 4) * 128 + d0 + (cc & 15);
        const float4 v = (k4 < 32) ? *(const float4*)&W_ih[wrow * 128 + k4 * 4]
                                   : *(const float4*)&W_hh[wrow * 128 + (k4 - 32) * 4];
        split_store(sB1 + cc * LDG2 + k4 * 4, sB2 + cc * LDG2 + k4 * 4, v);
    }

    PDL_WAIT();   // g_X must be complete

    #pragma unroll
    for (int i = t; i < 4096; i += 256) {
        const int row = i >> 6, k4 = i & 63;
        const float4 v = *(const float4*)&g_X[(row0 + row) * KX + k4 * 4];
        split_store(sA1 + row * LDG2 + k4 * 4, sA2 + row * LDG2 + k4 * 4, v);
    }
    __syncthreads();

    wmma::fragment<wmma::accumulator, 16, 16, 16, float> acc[2];
    wmma::fill_fragment(acc[0], 0.0f);
    wmma::fill_fragment(acc[1], 0.0f);
    wmma::fragment<wmma::matrix_a, 16, 16, 16, __nv_bfloat16, wmma::row_major> af;
    wmma::fragment<wmma::matrix_b, 16, 16, 16, __nv_bfloat16, wmma::col_major> bf[2];

    #pragma unroll
    for (int term = 0; term < 3; term++) {
        const __nv_bfloat16* sA = (term == 1) ? sA2 : sA1;
        const __nv_bfloat16* sB = (term == 2) ? sB2 : sB1;
        #pragma unroll
        for (int k0 = 0; k0 < 16; k0++) {
            wmma::load_matrix_sync(af, sA + (warp_m * 16) * LDG2 + k0 * 16, LDG2);
            #pragma unroll
            for (int j = 0; j < 2; j++) {
                wmma::load_matrix_sync(bf[j], sB + (warp_n * 32 + j * 16) * LDG2 + k0 * 16, LDG2);
                wmma::mma_sync(acc[j], af, bf[j], acc[j]);
            }
        }
    }

    #pragma unroll
    for (int j = 0; j < 2; j++)
        wmma::store_matrix_sync(sg + (warp_m * 16) * 68 + warp_n * 32 + j * 16,
                                acc[j], 68, wmma::mem_row_major);
    __syncthreads();

    #pragma unroll
    for (int idx = t; idx < 1024; idx += 256) {
        const int rl = idx >> 4;
        const int dd = idx & 15;
        const int d = d0 + dd;
        const float ig = sg[rl * 68 + dd]      + b_ih[d]       + b_hh[d];
        const float fg = sg[rl * 68 + 16 + dd] + b_ih[128 + d] + b_hh[128 + d];
        const float gg = sg[rl * 68 + 32 + dd] + b_ih[256 + d] + b_hh[256 + d];
        const float og = sg[rl * 68 + 48 + dd] + b_ih[384 + d] + b_hh[384 + d];
        const int n = row0 + rl;
        const float c = sigm(fg) * c0[n * HID + d] + sigm(ig) * tanhf(gg);
        g_h[n * HID + d] = sigm(og) * tanhf(c);
    }
}

// ============ K4: WMMA output projection (R10 version; W first, wait, then g_h) ============
#define LDO 136

__global__ __launch_bounds__(256) void out_kernel(const float* __restrict__ W_out,
                                                  const float* __restrict__ b_out,
                                                  float* __restrict__ out) {
    __shared__ __align__(16) __nv_bfloat16 sA1[16 * LDO];
    __shared__ __align__(16) __nv_bfloat16 sA2[16 * LDO];
    __shared__ __align__(16) __nv_bfloat16 sB1[64 * LDO];
    __shared__ __align__(16) __nv_bfloat16 sB2[64 * LDO];
    __shared__ float so[16 * 68];

    const int row0 = blockIdx.x * 16;
    const int col0 = blockIdx.y * 64;
    const int t   = threadIdx.x;
    const int wid = t >> 5;

    // independent prologue: W_out tile
    #pragma unroll
    for (int i = t; i < 2048; i += 256) {
        const int ee = i >> 5, k4 = i & 31;
        const int eg = col0 + ee;
        const float4 v = (eg < NOUT) ? *(const float4*)&W_out[eg * HID + k4 * 4]
                                     : make_float4(0.f, 0.f, 0.f, 0.f);
        split_store(sB1 + ee * LDO + k4 * 4, sB2 + ee * LDO + k4 * 4, v);
    }

    PDL_WAIT();   // g_h must be complete

    #pragma unroll
    for (int i = t; i < 512; i += 256) {
        const int row = i >> 5, k4 = i & 31;
        const float4 v = *(const float4*)&g_h[(row0 + row) * HID + k4 * 4];
        split_store(sA1 + row * LDO + k4 * 4, sA2 + row * LDO + k4 * 4, v);
    }
    __syncthreads();

    if (wid < 4) {
        wmma::fragment<wmma::accumulator, 16, 16, 16, float> acc;
        wmma::fill_fragment(acc, 0.0f);
        wmma::fragment<wmma::matrix_a, 16, 16, 16, __nv_bfloat16, wmma::row_major> af;
        wmma::fragment<wmma::matrix_b, 16, 16, 16, __nv_bfloat16, wmma::col_major> bf;
        #pragma unroll
        for (int term = 0; term < 3; term++) {
            const __nv_bfloat16* sA = (term == 1) ? sA2 : sA1;
            const __nv_bfloat16* sB = (term == 2) ? sB2 : sB1;
            #pragma unroll
            for (int k0 = 0; k0 < 8; k0++) {
                wmma::load_matrix_sync(af, sA + k0 * 16, LDO);
                wmma::load_matrix_sync(bf, sB + (wid * 16) * LDO + k0 * 16, LDO);
                wmma::mma_sync(acc, af, bf, acc);
            }
        }
        wmma::store_matrix_sync(so + wid * 16, acc, 68, wmma::mem_row_major);
    }
    __syncthreads();

    #pragma unroll
    for (int idx = t; idx < 16 * 64; idx += 256) {
        const int r  = idx >> 6;
        const int cc = idx & 63;
        const int e  = col0 + cc;
        if (e < NOUT) {
            const float v = so[r * 68 + cc] + b_out[e];
            out[(e / MIX) * (NP * MIX) + (row0 + r) * MIX + (e % MIX)] = v;
        }
    }
}

// ---------------- launch ----------------
extern "C" void kernel_launch(void* const* d_in, const int* in_sizes, int n_in,
                              void* d_out, int out_size) {
    const float* xabs  = (const float*)d_in[0];
    const float* h0    = (const float*)d_in[1];
    const float* c0    = (const float*)d_in[2];
    const float* W_emb = (const float*)d_in[3];
    const float* b_emb = (const float*)d_in[4];
    const float* W_soc = (const float*)d_in[5];
    const float* b_soc = (const float*)d_in[6];
    const float* W_ih  = (const float*)d_in[7];
    const float* W_hh  = (const float*)d_in[8];
    const float* b_ih  = (const float*)d_in[9];
    const float* b_hh  = (const float*)d_in[10];
    const float* W_out = (const float*)d_in[11];
    const float* b_out = (const float*)d_in[12];
    float* out = (float*)d_out;

    cudaFuncSetAttribute(mma_P_kernel, cudaFuncAttributeMaxDynamicSharedMemorySize, SMEM_P_BYTES);
    cudaFuncSetAttribute(gates_lstm_kernel, cudaFuncAttributeMaxDynamicSharedMemorySize, SMEM_G_BYTES);

    // K1: normal launch
    mma_P_kernel<<<dim3(8, 32), 256, SMEM_P_BYTES>>>(h0, W_soc);

    // K2..K4: programmatic dependent launches (prologues overlap predecessor)
    cudaLaunchAttribute attrs[1];
    attrs[0].id = cudaLaunchAttributeProgrammaticStreamSerialization;
    attrs[0].val.programmaticStreamSerializationAllowed = 1;

    {
        cudaLaunchConfig_t cfg = {};
        cfg.gridDim = dim3(NP, 1, 1);
        cfg.blockDim = dim3(512, 1, 1);
        cfg.dynamicSmemBytes = 0;
        cfg.stream = 0;
        cfg.attrs = attrs;
        cfg.numAttrs = 1;
        cudaLaunchKernelEx(&cfg, scatter_kernel, xabs, h0, W_emb, b_emb, b_soc);
    }
    {
        cudaLaunchConfig_t cfg = {};
        cfg.gridDim = dim3(16, 8, 1);
        cfg.blockDim = dim3(256, 1, 1);
        cfg.dynamicSmemBytes = SMEM_G_BYTES;
        cfg.stream = 0;
        cfg.attrs = attrs;
        cfg.numAttrs = 1;
        cudaLaunchKernelEx(&cfg, gates_lstm_kernel, W_ih, W_hh, b_ih, b_hh, c0);
    }
    {
        cudaLaunchConfig_t cfg = {};
        cfg.gridDim = dim3(64, 2, 1);
        cfg.blockDim = dim3(256, 1, 1);
        cfg.dynamicSmemBytes = 0;
        cfg.stream = 0;
        cfg.attrs = attrs;
        cfg.numAttrs = 1;
        cudaLaunchKernelEx(&cfg, out_kernel, W_out, b_out, out);
    }
}